// round 14
// baseline (speedup 1.0000x reference)
#include <cuda_runtime.h>
#include <cuda_fp16.h>
#include <cstdint>
#include <math.h>

#define SQ 4096
#define DM 768
#define FFD 3072
#define NH 12
#define DH 64
#define NMID 62
#define SCL 0.125f
#define NEGV (-1000000000.0f)
#define NSPL 16

__device__ float g_h[SQ * DM];
__device__ float g_q[SQ * DM];
__device__ float g_k[SQ * DM];
__device__ float g_v[SQ * DM];
__device__ float g_attn[SQ * DM];
__device__ float g_proj[SQ * DM];
__device__ float g_ffn[SQ * FFD];
__device__ float g_gpvp[NSPL * 24 * 64 * 64];
__device__ float g_gml[NSPL * 24 * 128];
__device__ float g_h1[512];

struct PlanParam { unsigned char rnd[NH][NMID][3]; };

namespace {
struct MT {
    uint32_t mt[624]; int mti;
    void seed(uint32_t s) {
        mt[0] = s;
        for (int i = 1; i < 624; i++)
            mt[i] = 1812433253u * (mt[i-1] ^ (mt[i-1] >> 30)) + (uint32_t)i;
        mti = 624;
    }
    uint32_t next() {
        if (mti >= 624) {
            for (int i = 0; i < 624; i++) {
                uint32_t y = (mt[i] & 0x80000000u) | (mt[(i+1)%624] & 0x7fffffffu);
                mt[i] = mt[(i+397)%624] ^ (y >> 1) ^ ((y & 1u) ? 0x9908b0dfu : 0u);
            }
            mti = 0;
        }
        uint32_t y = mt[mti++];
        y ^= y >> 11; y ^= (y << 7) & 0x9d2c5680u;
        y ^= (y << 15) & 0xefc60000u; y ^= y >> 18;
        return y;
    }
    uint32_t interval(uint32_t mx) {
        if (!mx) return 0;
        uint32_t m = mx;
        m |= m>>1; m |= m>>2; m |= m>>4; m |= m>>8; m |= m>>16;
        uint32_t v;
        while ((v = (next() & m)) > mx) {}
        return v;
    }
};
PlanParam build_plan() {
    PlanParam P; MT r; r.seed(0u);
    for (int h = 0; h < NH; h++)
        for (int i = 1; i <= NMID; i++) {
            bool inb[64] = {};
            inb[0] = inb[i-1] = inb[i] = inb[i+1] = inb[63] = true;
            int cand[64], nc = 0;
            for (int j = 1; j < 63; j++) if (!inb[j]) cand[nc++] = j;
            int perm[64];
            for (int t = 0; t < nc; t++) perm[t] = t;
            for (int t = nc - 1; t > 0; t--) {
                int j2 = (int)r.interval((uint32_t)t);
                int tmp = perm[t]; perm[t] = perm[j2]; perm[j2] = tmp;
            }
            for (int q = 0; q < 3; q++)
                P.rnd[h][i-1][q] = (unsigned char)cand[perm[q]];
        }
    return P;
}
PlanParam g_plan = build_plan();
}

__device__ __forceinline__ float gelu_t(float x) {
    float x3 = x * x * x;
    return 0.5f * x * (1.0f + tanhf(0.7978845608028654f * (x + 0.044715f * x3)));
}
__device__ __forceinline__ uint32_t f16pack2(float x0, float x1) {
    __half2 h = __floats2half2_rn(x0, x1);
    return *reinterpret_cast<uint32_t*>(&h);
}
__device__ __forceinline__ void f16split2(float x0, float x1, uint32_t& hi, uint32_t& lo) {
    __half2 h = __floats2half2_rn(x0, x1);
    hi = *reinterpret_cast<uint32_t*>(&h);
    float2 hf = __half22float2(h);
    __half2 l = __floats2half2_rn(x0 - hf.x, x1 - hf.y);
    lo = *reinterpret_cast<uint32_t*>(&l);
}
__device__ __forceinline__ float2 h2f2(uint32_t u) {
    __half2 h = *reinterpret_cast<__half2*>(&u);
    return __half22float2(h);
}
__device__ __forceinline__ void mmah(float* c, const uint32_t* a, const uint32_t* b) {
    asm("mma.sync.aligned.m16n8k16.row.col.f32.f16.f16.f32 "
        "{%0,%1,%2,%3},{%4,%5,%6,%7},{%8,%9},{%0,%1,%2,%3};"
        : "+f"(c[0]), "+f"(c[1]), "+f"(c[2]), "+f"(c[3])
        : "r"(a[0]), "r"(a[1]), "r"(a[2]), "r"(a[3]), "r"(b[0]), "r"(b[1]));
}
__device__ __forceinline__ void ldsm4(uint32_t& r0, uint32_t& r1, uint32_t& r2,
                                      uint32_t& r3, uint32_t addr) {
    asm volatile("ldmatrix.sync.aligned.m8n8.x4.shared.b16 {%0,%1,%2,%3}, [%4];"
                 : "=r"(r0), "=r"(r1), "=r"(r2), "=r"(r3) : "r"(addr));
}

// ---------------- fp16x2 tensor GEMM (R10 proven, unchanged) ----------------
#define PIT 20
#define APL (128 * PIT)
#define BPL (64 * PIT)
#define BUFU (APL + 2 * BPL)

__device__ __forceinline__ void tgemm_body(
    const float* __restrict__ A, const float* __restrict__ B,
    const float* __restrict__ bias, float* __restrict__ C,
    int N, int K, int act, int rb, int cb, uint32_t* smu) {
    int tid = threadIdx.x;
    int lane = tid & 31, wid = tid >> 5;
    int g = lane >> 2, q = lane & 3;
    int wr = (wid & 3) * 32, wc = (wid >> 2) * 32;
    float acc[2][4][4];
#pragma unroll
    for (int mi = 0; mi < 2; mi++)
#pragma unroll
        for (int ni = 0; ni < 4; ni++)
#pragma unroll
            for (int e = 0; e < 4; e++) acc[mi][ni][e] = 0.f;
    int arow = tid >> 3, akq = tid & 7;
    int bn = tid & 63, bkg = tid >> 6;
    const float* Bp = B + cb + bn;
    float4 pa[4];
    float pb[8];
    int ntile = K / 32;
    uint32_t sbase = (uint32_t)__cvta_generic_to_shared(smu);
    const uint32_t APLB = APL * 4, BPLB = BPL * 4;
    int a_r = wr + (lane & 15);
    int a_sel = (lane & 16) ? 4 : 0;
    int b_r = wc + (lane & 7) + ((lane & 16) ? 8 : 0);
    int b_sel = (lane & 8) ? 4 : 0;

#define LDAB(k0) { \
    _Pragma("unroll") \
    for (int u = 0; u < 4; u++) \
        pa[u] = *(const float4*)&A[(size_t)(rb + arow + u*32) * K + (k0) + akq*4]; \
    _Pragma("unroll") \
    for (int j = 0; j < 8; j++) \
        pb[j] = Bp[(size_t)((k0) + bkg*8 + j) * N]; }
#define STAB(buf) { \
    uint32_t* Ah = smu + (buf)*BUFU; \
    uint32_t* Bhi = Ah + APL; uint32_t* Blo = Bhi + BPL; \
    _Pragma("unroll") \
    for (int u = 0; u < 4; u++) { \
        uint32_t w0 = f16pack2(pa[u].x, pa[u].y); \
        uint32_t w1 = f16pack2(pa[u].z, pa[u].w); \
        int idx = (arow + u*32) * PIT + akq*2; \
        Ah[idx] = w0; Ah[idx+1] = w1; } \
    _Pragma("unroll") \
    for (int jj = 0; jj < 4; jj++) { \
        uint32_t hh,ll; \
        f16split2(pb[2*jj], pb[2*jj+1], hh, ll); \
        int idx = bn * PIT + bkg*4 + jj; \
        Bhi[idx] = hh; Blo[idx] = ll; } }

    LDAB(0); STAB(0);
    __syncthreads();
    for (int t = 0; t < ntile; t++) {
        int cur = t & 1;
        bool more = (t + 1) < ntile;
        if (more) LDAB((t + 1) * 32);
        uint32_t base = sbase + (uint32_t)cur * BUFU * 4;
#pragma unroll
        for (int s = 0; s < 2; s++) {
            uint32_t av[2][4], bh[4][2], bl[4][2];
#pragma unroll
            for (int mi = 0; mi < 2; mi++) {
                uint32_t off = (uint32_t)(((a_r + mi*16) * PIT) + s*8 + a_sel) * 4;
                ldsm4(av[mi][0], av[mi][1], av[mi][2], av[mi][3], base + off);
            }
#pragma unroll
            for (int np = 0; np < 2; np++) {
                uint32_t off = (uint32_t)(((b_r + np*16) * PIT) + s*8 + b_sel) * 4;
                ldsm4(bh[2*np][0], bh[2*np][1], bh[2*np+1][0], bh[2*np+1][1],
                      base + APLB + off);
                ldsm4(bl[2*np][0], bl[2*np][1], bl[2*np+1][0], bl[2*np+1][1],
                      base + APLB + BPLB + off);
            }
#pragma unroll
            for (int mi = 0; mi < 2; mi++)
#pragma unroll
                for (int ni = 0; ni < 4; ni++) {
                    mmah(acc[mi][ni], av[mi], bh[ni]);
                    mmah(acc[mi][ni], av[mi], bl[ni]);
                }
        }
        if (more) STAB(cur ^ 1);
        __syncthreads();
    }
#pragma unroll
    for (int mi = 0; mi < 2; mi++)
#pragma unroll
        for (int ni = 0; ni < 4; ni++) {
            int col = cb + wc + ni * 8 + 2 * q;
            float b0 = bias[col], b1 = bias[col + 1];
            int r0 = rb + wr + mi * 16 + g;
            float v0 = acc[mi][ni][0] + b0, v1 = acc[mi][ni][1] + b1;
            float v2 = acc[mi][ni][2] + b0, v3 = acc[mi][ni][3] + b1;
            if (act) { v0 = gelu_t(v0); v1 = gelu_t(v1); v2 = gelu_t(v2); v3 = gelu_t(v3); }
            float2 w0 = {v0, v1}, w1 = {v2, v3};
            *(float2*)&C[(size_t)r0 * N + col] = w0;
            *(float2*)&C[(size_t)(r0 + 8) * N + col] = w1;
        }
#undef LDAB
#undef STAB
}

__global__ __launch_bounds__(256, 2)
void tgemm(const float* __restrict__ A, const float* __restrict__ B,
           const float* __restrict__ bias, float* __restrict__ C,
           int M, int N, int K, int act) {
    extern __shared__ uint32_t smu[];
    tgemm_body(A, B, bias, C, N, K, act, blockIdx.y * 128, blockIdx.x * 64, smu);
}
__global__ __launch_bounds__(256, 2)
void tgemm3(const float* __restrict__ A,
            const float* __restrict__ B0, const float* __restrict__ B1,
            const float* __restrict__ B2,
            const float* __restrict__ s0, const float* __restrict__ s1,
            const float* __restrict__ s2,
            float* __restrict__ C0, float* __restrict__ C1,
            float* __restrict__ C2, int N, int K) {
    extern __shared__ uint32_t smu[];
    const float* B = (blockIdx.z == 0) ? B0 : (blockIdx.z == 1) ? B1 : B2;
    const float* s = (blockIdx.z == 0) ? s0 : (blockIdx.z == 1) ? s1 : s2;
    float* C = (blockIdx.z == 0) ? C0 : (blockIdx.z == 1) ? C1 : C2;
    tgemm_body(A, B, s, C, N, K, 0, blockIdx.y * 128, blockIdx.x * 64, smu);
}

// ------------------- add + LayerNorm: one warp per row ----------------------
__global__ __launch_bounds__(256)
void add_ln(float* __restrict__ out, const float* __restrict__ a,
            const float* __restrict__ b, const float* __restrict__ pos,
            const float* __restrict__ tok, const float* __restrict__ g,
            const float* __restrict__ be) {
    int row = blockIdx.x * 8 + (threadIdx.x >> 5);
    int lane = threadIdx.x & 31;
    float v[24], s = 0.f;
#pragma unroll
    for (int u = 0; u < 24; u++) {
        int c = lane + u * 32;
        float t = a[(size_t)row * DM + c];
        if (b) t += b[(size_t)row * DM + c];
        if (pos) t += pos[(size_t)row * DM + c];
        if (tok) t += tok[c];
        v[u] = t; s += t;
    }
#pragma unroll
    for (int o = 16; o; o >>= 1) s += __shfl_xor_sync(~0u, s, o);
    float mean = s * (1.f / 768.f), qv = 0.f;
#pragma unroll
    for (int u = 0; u < 24; u++) { float d = v[u] - mean; qv += d * d; }
#pragma unroll
    for (int o = 16; o; o >>= 1) qv += __shfl_xor_sync(~0u, qv, o);
    float inv = rsqrtf(qv * (1.f / 768.f) + 1e-12f);
#pragma unroll
    for (int u = 0; u < 24; u++) {
        int c = lane + u * 32;
        out[(size_t)row * DM + c] = (v[u] - mean) * inv * g[c] + be[c];
    }
}

// ================ flash-mma attention (R12 proven core) ======================
#define PIT2 36
#define PL2 (64 * PIT2)
#define QHIO 0
#define QLOO PL2
#define KHIO (2 * PL2)
#define KLOO (3 * PL2)
#define VHIO (4 * PL2)
#define VLOO (5 * PL2)
#define MSKO (6 * PL2)
#define SMATT ((6 * PL2 + 64) * 4)

__device__ __forceinline__ void stage_rowplane(const float* src, uint32_t* hi,
                                               uint32_t* lo, int tid) {
#pragma unroll
    for (int w = 0; w < 16; w++) {
        int idx = w * 128 + tid;
        int row = idx >> 5, j = idx & 31;
        float2 v = *(const float2*)(src + (size_t)row * DM + 2 * j);
        uint32_t h, l; f16split2(v.x, v.y, h, l);
        hi[row * PIT2 + j] = h; lo[row * PIT2 + j] = l;
    }
}
__device__ __forceinline__ void stage_vt(const float* src, uint32_t* hi,
                                         uint32_t* lo, int tid) {
#pragma unroll
    for (int w = 0; w < 16; w++) {
        int idx = w * 128 + tid;
        int d = idx & 63, j = idx >> 6;
        float v0 = src[(size_t)(2 * j) * DM + d];
        float v1 = src[(size_t)(2 * j + 1) * DM + d];
        uint32_t h, l; f16split2(v0, v1, h, l);
        hi[d * PIT2 + j] = h; lo[d * PIT2 + j] = l;
    }
}

__device__ __forceinline__ void flash_block(
    uint32_t smb, const uint32_t* msk, int lane,
    const uint32_t (&qh)[4][4], const uint32_t (&ql)[4][4],
    float (&oacc)[8][4], float& M0, float& M1, float& L0, float& L1) {
    int q = lane & 3;
    int b_rb = (lane & 7) + ((lane & 16) ? 8 : 0);
    int b_sel = (lane & 8) ? 4 : 0;
    float s[8][4];
#pragma unroll
    for (int t = 0; t < 8; t++)
#pragma unroll
        for (int e = 0; e < 4; e++) s[t][e] = 0.f;
#pragma unroll
    for (int c = 0; c < 4; c++) {
#pragma unroll
        for (int np = 0; np < 4; np++) {
            uint32_t off = (uint32_t)(((np * 16 + b_rb) * PIT2) + c * 8 + b_sel) * 4;
            uint32_t h0, h1, h2, h3, l0, l1, l2, l3;
            ldsm4(h0, h1, h2, h3, smb + KHIO * 4 + off);
            ldsm4(l0, l1, l2, l3, smb + KLOO * 4 + off);
            uint32_t bh0[2] = {h0, h1}, bh1[2] = {h2, h3};
            uint32_t bl0[2] = {l0, l1}, bl1[2] = {l2, l3};
            mmah(s[2*np],   qh[c], bh0); mmah(s[2*np],   ql[c], bh0); mmah(s[2*np],   qh[c], bl0);
            mmah(s[2*np+1], qh[c], bh1); mmah(s[2*np+1], ql[c], bh1); mmah(s[2*np+1], qh[c], bl1);
        }
    }
#pragma unroll
    for (int t = 0; t < 8; t++) {
        int c0 = t * 8 + 2 * q;
        bool m0 = msk[c0] != 0, m1 = msk[c0 + 1] != 0;
        s[t][0] = m0 ? s[t][0] * SCL : NEGV;
        s[t][1] = m1 ? s[t][1] * SCL : NEGV;
        s[t][2] = m0 ? s[t][2] * SCL : NEGV;
        s[t][3] = m1 ? s[t][3] * SCL : NEGV;
    }
    float mx0 = -3.4e38f, mx1 = -3.4e38f;
#pragma unroll
    for (int t = 0; t < 8; t++) {
        mx0 = fmaxf(mx0, fmaxf(s[t][0], s[t][1]));
        mx1 = fmaxf(mx1, fmaxf(s[t][2], s[t][3]));
    }
    mx0 = fmaxf(mx0, __shfl_xor_sync(~0u, mx0, 1));
    mx0 = fmaxf(mx0, __shfl_xor_sync(~0u, mx0, 2));
    mx1 = fmaxf(mx1, __shfl_xor_sync(~0u, mx1, 1));
    mx1 = fmaxf(mx1, __shfl_xor_sync(~0u, mx1, 2));
    float nM0 = fmaxf(M0, mx0), nM1 = fmaxf(M1, mx1);
    float cr0 = __expf(M0 - nM0), cr1 = __expf(M1 - nM1);
    float r0 = 0.f, r1 = 0.f;
#pragma unroll
    for (int t = 0; t < 8; t++) {
        s[t][0] = __expf(s[t][0] - nM0); s[t][1] = __expf(s[t][1] - nM0);
        s[t][2] = __expf(s[t][2] - nM1); s[t][3] = __expf(s[t][3] - nM1);
        r0 += s[t][0] + s[t][1]; r1 += s[t][2] + s[t][3];
    }
    r0 += __shfl_xor_sync(~0u, r0, 1); r0 += __shfl_xor_sync(~0u, r0, 2);
    r1 += __shfl_xor_sync(~0u, r1, 1); r1 += __shfl_xor_sync(~0u, r1, 2);
    L0 = L0 * cr0 + r0; L1 = L1 * cr1 + r1; M0 = nM0; M1 = nM1;
#pragma unroll
    for (int t = 0; t < 8; t++) {
        oacc[t][0] *= cr0; oacc[t][1] *= cr0;
        oacc[t][2] *= cr1; oacc[t][3] *= cr1;
    }
#pragma unroll
    for (int kc = 0; kc < 4; kc++) {
        int t0 = 2 * kc, t1 = t0 + 1;
        uint32_t pa[4], pl[4];
        pa[0] = f16pack2(s[t0][0], s[t0][1]);
        pa[1] = f16pack2(s[t0][2], s[t0][3]);
        pa[2] = f16pack2(s[t1][0], s[t1][1]);
        pa[3] = f16pack2(s[t1][2], s[t1][3]);
        {
            float2 f;
            f = h2f2(pa[0]); pl[0] = f16pack2(s[t0][0] - f.x, s[t0][1] - f.y);
            f = h2f2(pa[1]); pl[1] = f16pack2(s[t0][2] - f.x, s[t0][3] - f.y);
            f = h2f2(pa[2]); pl[2] = f16pack2(s[t1][0] - f.x, s[t1][1] - f.y);
            f = h2f2(pa[3]); pl[3] = f16pack2(s[t1][2] - f.x, s[t1][3] - f.y);
        }
#pragma unroll
        for (int np = 0; np < 4; np++) {
            uint32_t off = (uint32_t)(((np * 16 + b_rb) * PIT2) + kc * 8 + b_sel) * 4;
            uint32_t h0, h1, h2, h3, l0, l1, l2, l3;
            ldsm4(h0, h1, h2, h3, smb + VHIO * 4 + off);
            ldsm4(l0, l1, l2, l3, smb + VLOO * 4 + off);
            uint32_t bh0[2] = {h0, h1}, bh1[2] = {h2, h3};
            uint32_t bl0[2] = {l0, l1}, bl1[2] = {l2, l3};
            mmah(oacc[2*np],   pa, bh0); mmah(oacc[2*np],   pl, bh0); mmah(oacc[2*np],   pa, bl0);
            mmah(oacc[2*np+1], pa, bh1); mmah(oacc[2*np+1], pl, bh1); mmah(oacc[2*np+1], pa, bl1);
        }
    }
}

// merged global + middle attention: one launch, 24*NSPL + 62*12 CTAs
__global__ __launch_bounds__(128)
void attnall(const float* __restrict__ Q, const float* __restrict__ K,
             const float* __restrict__ V, const int* __restrict__ am,
             float* __restrict__ part, float* __restrict__ ml,
             float* __restrict__ O, PlanParam plan) {
    extern __shared__ uint32_t sm[];
    int tid = threadIdx.x, lane = tid & 31, wid = tid >> 5;
    uint32_t smb = (uint32_t)__cvta_generic_to_shared(sm);
    int bx = blockIdx.x;
    bool isglob = bx < 24 * NSPL;
    int blks[8]; bool vl[8];
    int nblk, qoff, h, pt = 0, hg = 0, i = 0;
    if (isglob) {
        pt = bx / 24; hg = bx % 24; h = hg >> 1;
        qoff = (hg & 1) ? (SQ - 64) : 0;
        nblk = 64 / NSPL;
        for (int j = 0; j < nblk; j++) { blks[j] = pt * nblk + j; vl[j] = true; }
    } else {
        int j = bx - 24 * NSPL;
        int im = j % 62; h = j / 62; i = im + 1;
        qoff = i * 64; nblk = 8;
        blks[0] = 0; blks[1] = i - 1; blks[2] = i; blks[3] = i + 1; blks[4] = 63;
        blks[5] = plan.rnd[h][im][0]; blks[6] = plan.rnd[h][im][1]; blks[7] = plan.rnd[h][im][2];
        vl[0] = true; vl[1] = (i != 1); vl[2] = true; vl[3] = true; vl[4] = (i != 62);
        vl[5] = vl[6] = vl[7] = true;
    }
    stage_rowplane(Q + (size_t)qoff * DM + h * DH, sm + QHIO, sm + QLOO, tid);
    __syncthreads();
    uint32_t qh[4][4], ql[4][4];
    {
        int a_row = wid * 16 + (lane & 15);
        int a_sel = (lane & 16) ? 4 : 0;
#pragma unroll
        for (int c = 0; c < 4; c++) {
            uint32_t off = (uint32_t)(a_row * PIT2 + c * 8 + a_sel) * 4;
            ldsm4(qh[c][0], qh[c][1], qh[c][2], qh[c][3], smb + QHIO * 4 + off);
            ldsm4(ql[c][0], ql[c][1], ql[c][2], ql[c][3], smb + QLOO * 4 + off);
        }
    }
    float oacc[8][4];
#pragma unroll
    for (int t = 0; t < 8; t++)
#pragma unroll
        for (int e = 0; e < 4; e++) oacc[t][e] = 0.f;
    float M0 = -3.4e38f, M1 = -3.4e38f, L0 = 0.f, L1 = 0.f;
    for (int c = 0; c < nblk; c++) {
        stage_rowplane(K + (size_t)(blks[c] * 64) * DM + h * DH, sm + KHIO, sm + KLOO, tid);
        stage_vt(V + (size_t)(blks[c] * 64) * DM + h * DH, sm + VHIO, sm + VLOO, tid);
        if (tid < 64) sm[MSKO + tid] = (vl[c] && am[blks[c] * 64 + tid] > 0) ? 1u : 0u;
        __syncthreads();
        flash_block(smb, sm + MSKO, lane, qh, ql, oacc, M0, M1, L0, L1);
        __syncthreads();
    }
    int g = lane >> 2, q = lane & 3;
    int r0 = wid * 16 + g, r1 = r0 + 8;
    if (isglob) {
        float* dst = part + ((size_t)(pt * 24 + hg) << 12);
#pragma unroll
        for (int t = 0; t < 8; t++) {
            int col = t * 8 + 2 * q;
            float2 w0 = {oacc[t][0], oacc[t][1]};
            float2 w1 = {oacc[t][2], oacc[t][3]};
            *(float2*)&dst[r0 * 64 + col] = w0;
            *(float2*)&dst[r1 * 64 + col] = w1;
        }
        if (q == 0) {
            int base = (pt * 24 + hg) * 128;
            ml[base + r0] = M0; ml[base + 64 + r0] = L0;
            ml[base + r1] = M1; ml[base + 64 + r1] = L1;
        }
    } else {
        float inv0 = 1.f / L0, inv1 = 1.f / L1;
#pragma unroll
        for (int t = 0; t < 8; t++) {
            int col = t * 8 + 2 * q;
            float2 w0 = {oacc[t][0] * inv0, oacc[t][1] * inv0};
            float2 w1 = {oacc[t][2] * inv1, oacc[t][3] * inv1};
            *(float2*)&O[(size_t)(qoff + r0) * DM + h * DH + col] = w0;
            *(float2*)&O[(size_t)(qoff + r1) * DM + h * DH + col] = w1;
        }
    }
}

__global__ __launch_bounds__(256)
void gflash_red(const float* __restrict__ part, const float* __restrict__ ml,
                float* __restrict__ O) {
    int idx = blockIdx.x * 256 + threadIdx.x;
    int hg = idx >> 12, off = idx & 4095;
    int h = hg >> 1, qb = (hg & 1) ? (SQ - 64) : 0;
    int r = off >> 6, c = off & 63;
    float Mv[NSPL], Lv[NSPL];
    float gM = -3.4e38f;
#pragma unroll
    for (int pt = 0; pt < NSPL; pt++) {
        Mv[pt] = ml[(pt * 24 + hg) * 128 + r];
        Lv[pt] = ml[(pt * 24 + hg) * 128 + 64 + r];
        gM = fmaxf(gM, Mv[pt]);
    }
    float Lt = 0.f, s = 0.f;
#pragma unroll
    for (int pt = 0; pt < NSPL; pt++) {
        float w = __expf(Mv[pt] - gM);
        Lt += Lv[pt] * w;
        s += part[((size_t)(pt * 24 + hg) << 12) + off] * w;
    }
    O[(size_t)(qb + r) * DM + h * DH + c] = s / Lt;
}

// ------------------------------ classifier ----------------------------------
__global__ __launch_bounds__(512)
void cls_fc1(const float* __restrict__ h, const float* __restrict__ W,
             const float* __restrict__ b, float* __restrict__ o) {
    int n = threadIdx.x;
    float s = b[n];
    for (int k = 0; k < DM; k++) s += h[k] * W[(size_t)k * 512 + n];
    o[n] = fmaxf(s, 0.f);
}
__global__ __launch_bounds__(256)
void cls_fc2(const float* __restrict__ h1, const float* __restrict__ W,
             const float* __restrict__ b, float* __restrict__ o) {
    int n = blockIdx.x * 256 + threadIdx.x;
    if (n >= 2000) return;
    float s = b[n];
    for (int k = 0; k < 512; k++) s += h1[k] * W[(size_t)k * 2000 + n];
    o[n] = s;
}

// ------------------------------ launch --------------------------------------
extern "C" void kernel_launch(void* const* d_in, const int* in_sizes, int n_in,
                              void* d_out, int out_size) {
    const float* x    = (const float*)d_in[0];
    const int*   am   = (const int*)d_in[1];
    const float* Wp   = (const float*)d_in[2];
    const float* bp   = (const float*)d_in[3];
    const float* pos  = (const float*)d_in[4];
    const float* tok  = (const float*)d_in[5];
    const float* lng  = (const float*)d_in[6];
    const float* lnb  = (const float*)d_in[7];
    const float* Wq   = (const float*)d_in[8];
    const float* bq   = (const float*)d_in[9];
    const float* Wk   = (const float*)d_in[10];
    const float* bk   = (const float*)d_in[11];
    const float* Wv   = (const float*)d_in[12];
    const float* bv   = (const float*)d_in[13];
    const float* Wo   = (const float*)d_in[14];
    const float* bo   = (const float*)d_in[15];
    const float* l1g  = (const float*)d_in[16];
    const float* l1b  = (const float*)d_in[17];
    const float* W1   = (const float*)d_in[18];
    const float* b1f  = (const float*)d_in[19];
    const float* W2   = (const float*)d_in[20];
    const float* b2f  = (const float*)d_in[21];
    const float* l2g  = (const float*)d_in[22];
    const float* l2b  = (const float*)d_in[23];
    const float* Wc1  = (const float*)d_in[24];
    const float* bc1  = (const float*)d_in[25];
    const float* Wc2  = (const float*)d_in[26];
    const float* bc2  = (const float*)d_in[27];

    float *h, *q, *k, *v, *attn, *proj, *ffn, *gpvp, *gml, *h1;
    cudaGetSymbolAddress((void**)&h, g_h);
    cudaGetSymbolAddress((void**)&q, g_q);
    cudaGetSymbolAddress((void**)&k, g_k);
    cudaGetSymbolAddress((void**)&v, g_v);
    cudaGetSymbolAddress((void**)&attn, g_attn);
    cudaGetSymbolAddress((void**)&proj, g_proj);
    cudaGetSymbolAddress((void**)&ffn, g_ffn);
    cudaGetSymbolAddress((void**)&gpvp, g_gpvp);
    cudaGetSymbolAddress((void**)&gml, g_gml);
    cudaGetSymbolAddress((void**)&h1, g_h1);

    cudaFuncSetAttribute(attnall, cudaFuncAttributeMaxDynamicSharedMemorySize, SMATT);
    int smgemm = 2 * BUFU * 4;
    cudaFuncSetAttribute(tgemm, cudaFuncAttributeMaxDynamicSharedMemorySize, smgemm);
    cudaFuncSetAttribute(tgemm3, cudaFuncAttributeMaxDynamicSharedMemorySize, smgemm);

    dim3 gP(DM / 64, SQ / 128);
    dim3 gF(FFD / 64, SQ / 128);
    dim3 gQKV(DM / 64, SQ / 128, 3);
    int nAttn = 24 * NSPL + 62 * 12;

    tgemm<<<gP, 256, smgemm>>>(x, Wp, bp, proj, SQ, DM, 1280, 0);
    add_ln<<<SQ / 8, 256>>>(h, proj, nullptr, pos, tok, lng, lnb);

    for (int l = 0; l < 12; l++) {
        const float* wq = Wq + (size_t)l*DM*DM; const float* bql = bq + (size_t)l*DM;
        const float* wk = Wk + (size_t)l*DM*DM; const float* bkl = bk + (size_t)l*DM;
        const float* wv = Wv + (size_t)l*DM*DM; const float* bvl = bv + (size_t)l*DM;
        const float* wo = Wo + (size_t)l*DM*DM; const float* bol = bo + (size_t)l*DM;
        const float* w1 = W1 + (size_t)l*DM*FFD; const float* b1l = b1f + (size_t)l*FFD;
        const float* w2 = W2 + (size_t)l*FFD*DM; const float* b2l = b2f + (size_t)l*DM;

        tgemm3<<<gQKV, 256, smgemm>>>(h, wq, wk, wv, bql, bkl, bvl, q, k, v, DM, DM);

        attnall<<<nAttn, 128, SMATT>>>(q, k, v, am, gpvp, gml, attn, g_plan);
        gflash_red<<<(24 * 4096) / 256, 256>>>(gpvp, gml, attn);

        tgemm<<<gP, 256, smgemm>>>(attn, wo, bol, proj, SQ, DM, DM, 0);
        add_ln<<<SQ / 8, 256>>>(h, h, proj, nullptr, nullptr, l1g + (size_t)l*DM, l1b + (size_t)l*DM);
        tgemm<<<gF, 256, smgemm>>>(h, w1, b1l, ffn, SQ, FFD, DM, 1);
        tgemm<<<gP, 256, smgemm>>>(ffn, w2, b2l, proj, SQ, DM, FFD, 0);
        add_ln<<<SQ / 8, 256>>>(h, h, proj, nullptr, nullptr, l2g + (size_t)l*DM, l2b + (size_t)l*DM);
    }

    cls_fc1<<<1, 512>>>(h, Wc1, bc1, h1);
    cls_fc2<<<8, 256>>>(h1, Wc2, bc2, (float*)d_out);
}

// round 15
// speedup vs baseline: 1.0542x; 1.0542x over previous
#include <cuda_runtime.h>
#include <cuda_fp16.h>
#include <cstdint>
#include <math.h>

#define SQ 4096
#define DM 768
#define FFD 3072
#define NH 12
#define DH 64
#define NMID 62
#define SCL 0.125f
#define NEGV (-1000000000.0f)
#define NSPL 16

__device__ float g_h[SQ * DM];
__device__ float g_q[SQ * DM];
__device__ float g_k[SQ * DM];
__device__ float g_v[SQ * DM];
__device__ float g_attn[SQ * DM];
__device__ float g_proj[SQ * DM];
__device__ float g_ffn[SQ * FFD];
__device__ float g_gpvp[NSPL * 24 * 64 * 64];
__device__ float g_gml[NSPL * 24 * 128];
__device__ float g_h1[512];

struct PlanParam { unsigned char rnd[NH][NMID][3]; };

namespace {
struct MT {
    uint32_t mt[624]; int mti;
    void seed(uint32_t s) {
        mt[0] = s;
        for (int i = 1; i < 624; i++)
            mt[i] = 1812433253u * (mt[i-1] ^ (mt[i-1] >> 30)) + (uint32_t)i;
        mti = 624;
    }
    uint32_t next() {
        if (mti >= 624) {
            for (int i = 0; i < 624; i++) {
                uint32_t y = (mt[i] & 0x80000000u) | (mt[(i+1)%624] & 0x7fffffffu);
                mt[i] = mt[(i+397)%624] ^ (y >> 1) ^ ((y & 1u) ? 0x9908b0dfu : 0u);
            }
            mti = 0;
        }
        uint32_t y = mt[mti++];
        y ^= y >> 11; y ^= (y << 7) & 0x9d2c5680u;
        y ^= (y << 15) & 0xefc60000u; y ^= y >> 18;
        return y;
    }
    uint32_t interval(uint32_t mx) {
        if (!mx) return 0;
        uint32_t m = mx;
        m |= m>>1; m |= m>>2; m |= m>>4; m |= m>>8; m |= m>>16;
        uint32_t v;
        while ((v = (next() & m)) > mx) {}
        return v;
    }
};
PlanParam build_plan() {
    PlanParam P; MT r; r.seed(0u);
    for (int h = 0; h < NH; h++)
        for (int i = 1; i <= NMID; i++) {
            bool inb[64] = {};
            inb[0] = inb[i-1] = inb[i] = inb[i+1] = inb[63] = true;
            int cand[64], nc = 0;
            for (int j = 1; j < 63; j++) if (!inb[j]) cand[nc++] = j;
            int perm[64];
            for (int t = 0; t < nc; t++) perm[t] = t;
            for (int t = nc - 1; t > 0; t--) {
                int j2 = (int)r.interval((uint32_t)t);
                int tmp = perm[t]; perm[t] = perm[j2]; perm[j2] = tmp;
            }
            for (int q = 0; q < 3; q++)
                P.rnd[h][i-1][q] = (unsigned char)cand[perm[q]];
        }
    return P;
}
PlanParam g_plan = build_plan();
}

__device__ __forceinline__ float gelu_t(float x) {
    float x3 = x * x * x;
    return 0.5f * x * (1.0f + tanhf(0.7978845608028654f * (x + 0.044715f * x3)));
}
__device__ __forceinline__ uint32_t f16pack2(float x0, float x1) {
    __half2 h = __floats2half2_rn(x0, x1);
    return *reinterpret_cast<uint32_t*>(&h);
}
__device__ __forceinline__ void f16split2(float x0, float x1, uint32_t& hi, uint32_t& lo) {
    __half2 h = __floats2half2_rn(x0, x1);
    hi = *reinterpret_cast<uint32_t*>(&h);
    float2 hf = __half22float2(h);
    __half2 l = __floats2half2_rn(x0 - hf.x, x1 - hf.y);
    lo = *reinterpret_cast<uint32_t*>(&l);
}
__device__ __forceinline__ float2 h2f2(uint32_t u) {
    __half2 h = *reinterpret_cast<__half2*>(&u);
    return __half22float2(h);
}
__device__ __forceinline__ void mmah(float* c, const uint32_t* a, const uint32_t* b) {
    asm("mma.sync.aligned.m16n8k16.row.col.f32.f16.f16.f32 "
        "{%0,%1,%2,%3},{%4,%5,%6,%7},{%8,%9},{%0,%1,%2,%3};"
        : "+f"(c[0]), "+f"(c[1]), "+f"(c[2]), "+f"(c[3])
        : "r"(a[0]), "r"(a[1]), "r"(a[2]), "r"(a[3]), "r"(b[0]), "r"(b[1]));
}
__device__ __forceinline__ void ldsm4(uint32_t& r0, uint32_t& r1, uint32_t& r2,
                                      uint32_t& r3, uint32_t addr) {
    asm volatile("ldmatrix.sync.aligned.m8n8.x4.shared.b16 {%0,%1,%2,%3}, [%4];"
                 : "=r"(r0), "=r"(r1), "=r"(r2), "=r"(r3) : "r"(addr));
}

// ---------------- fp16x2 tensor GEMM (R10 proven, unchanged) ----------------
#define PIT 20
#define APL (128 * PIT)
#define BPL (64 * PIT)
#define BUFU (APL + 2 * BPL)

__device__ __forceinline__ void tgemm_body(
    const float* __restrict__ A, const float* __restrict__ B,
    const float* __restrict__ bias, float* __restrict__ C,
    int N, int K, int act, int rb, int cb, uint32_t* smu) {
    int tid = threadIdx.x;
    int lane = tid & 31, wid = tid >> 5;
    int g = lane >> 2, q = lane & 3;
    int wr = (wid & 3) * 32, wc = (wid >> 2) * 32;
    float acc[2][4][4];
#pragma unroll
    for (int mi = 0; mi < 2; mi++)
#pragma unroll
        for (int ni = 0; ni < 4; ni++)
#pragma unroll
            for (int e = 0; e < 4; e++) acc[mi][ni][e] = 0.f;
    int arow = tid >> 3, akq = tid & 7;
    int bn = tid & 63, bkg = tid >> 6;
    const float* Bp = B + cb + bn;
    float4 pa[4];
    float pb[8];
    int ntile = K / 32;
    uint32_t sbase = (uint32_t)__cvta_generic_to_shared(smu);
    const uint32_t APLB = APL * 4, BPLB = BPL * 4;
    int a_r = wr + (lane & 15);
    int a_sel = (lane & 16) ? 4 : 0;
    int b_r = wc + (lane & 7) + ((lane & 16) ? 8 : 0);
    int b_sel = (lane & 8) ? 4 : 0;

#define LDAB(k0) { \
    _Pragma("unroll") \
    for (int u = 0; u < 4; u++) \
        pa[u] = *(const float4*)&A[(size_t)(rb + arow + u*32) * K + (k0) + akq*4]; \
    _Pragma("unroll") \
    for (int j = 0; j < 8; j++) \
        pb[j] = Bp[(size_t)((k0) + bkg*8 + j) * N]; }
#define STAB(buf) { \
    uint32_t* Ah = smu + (buf)*BUFU; \
    uint32_t* Bhi = Ah + APL; uint32_t* Blo = Bhi + BPL; \
    _Pragma("unroll") \
    for (int u = 0; u < 4; u++) { \
        uint32_t w0 = f16pack2(pa[u].x, pa[u].y); \
        uint32_t w1 = f16pack2(pa[u].z, pa[u].w); \
        int idx = (arow + u*32) * PIT + akq*2; \
        Ah[idx] = w0; Ah[idx+1] = w1; } \
    _Pragma("unroll") \
    for (int jj = 0; jj < 4; jj++) { \
        uint32_t hh,ll; \
        f16split2(pb[2*jj], pb[2*jj+1], hh, ll); \
        int idx = bn * PIT + bkg*4 + jj; \
        Bhi[idx] = hh; Blo[idx] = ll; } }

    LDAB(0); STAB(0);
    __syncthreads();
    for (int t = 0; t < ntile; t++) {
        int cur = t & 1;
        bool more = (t + 1) < ntile;
        if (more) LDAB((t + 1) * 32);
        uint32_t base = sbase + (uint32_t)cur * BUFU * 4;
#pragma unroll
        for (int s = 0; s < 2; s++) {
            uint32_t av[2][4], bh[4][2], bl[4][2];
#pragma unroll
            for (int mi = 0; mi < 2; mi++) {
                uint32_t off = (uint32_t)(((a_r + mi*16) * PIT) + s*8 + a_sel) * 4;
                ldsm4(av[mi][0], av[mi][1], av[mi][2], av[mi][3], base + off);
            }
#pragma unroll
            for (int np = 0; np < 2; np++) {
                uint32_t off = (uint32_t)(((b_r + np*16) * PIT) + s*8 + b_sel) * 4;
                ldsm4(bh[2*np][0], bh[2*np][1], bh[2*np+1][0], bh[2*np+1][1],
                      base + APLB + off);
                ldsm4(bl[2*np][0], bl[2*np][1], bl[2*np+1][0], bl[2*np+1][1],
                      base + APLB + BPLB + off);
            }
#pragma unroll
            for (int mi = 0; mi < 2; mi++)
#pragma unroll
                for (int ni = 0; ni < 4; ni++) {
                    mmah(acc[mi][ni], av[mi], bh[ni]);
                    mmah(acc[mi][ni], av[mi], bl[ni]);
                }
        }
        if (more) STAB(cur ^ 1);
        __syncthreads();
    }
#pragma unroll
    for (int mi = 0; mi < 2; mi++)
#pragma unroll
        for (int ni = 0; ni < 4; ni++) {
            int col = cb + wc + ni * 8 + 2 * q;
            float b0 = bias[col], b1 = bias[col + 1];
            int r0 = rb + wr + mi * 16 + g;
            float v0 = acc[mi][ni][0] + b0, v1 = acc[mi][ni][1] + b1;
            float v2 = acc[mi][ni][2] + b0, v3 = acc[mi][ni][3] + b1;
            if (act) { v0 = gelu_t(v0); v1 = gelu_t(v1); v2 = gelu_t(v2); v3 = gelu_t(v3); }
            float2 w0 = {v0, v1}, w1 = {v2, v3};
            *(float2*)&C[(size_t)r0 * N + col] = w0;
            *(float2*)&C[(size_t)(r0 + 8) * N + col] = w1;
        }
#undef LDAB
#undef STAB
}

__global__ __launch_bounds__(256, 2)
void tgemm(const float* __restrict__ A, const float* __restrict__ B,
           const float* __restrict__ bias, float* __restrict__ C,
           int M, int N, int K, int act) {
    extern __shared__ uint32_t smu[];
    tgemm_body(A, B, bias, C, N, K, act, blockIdx.y * 128, blockIdx.x * 64, smu);
}
__global__ __launch_bounds__(256, 2)
void tgemm3(const float* __restrict__ A,
            const float* __restrict__ B0, const float* __restrict__ B1,
            const float* __restrict__ B2,
            const float* __restrict__ s0, const float* __restrict__ s1,
            const float* __restrict__ s2,
            float* __restrict__ C0, float* __restrict__ C1,
            float* __restrict__ C2, int N, int K) {
    extern __shared__ uint32_t smu[];
    const float* B = (blockIdx.z == 0) ? B0 : (blockIdx.z == 1) ? B1 : B2;
    const float* s = (blockIdx.z == 0) ? s0 : (blockIdx.z == 1) ? s1 : s2;
    float* C = (blockIdx.z == 0) ? C0 : (blockIdx.z == 1) ? C1 : C2;
    tgemm_body(A, B, s, C, N, K, 0, blockIdx.y * 128, blockIdx.x * 64, smu);
}

// ------------------- add + LayerNorm: one warp per row ----------------------
__global__ __launch_bounds__(256)
void add_ln(float* __restrict__ out, const float* __restrict__ a,
            const float* __restrict__ b, const float* __restrict__ pos,
            const float* __restrict__ tok, const float* __restrict__ g,
            const float* __restrict__ be) {
    int row = blockIdx.x * 8 + (threadIdx.x >> 5);
    int lane = threadIdx.x & 31;
    float v[24], s = 0.f;
#pragma unroll
    for (int u = 0; u < 24; u++) {
        int c = lane + u * 32;
        float t = a[(size_t)row * DM + c];
        if (b) t += b[(size_t)row * DM + c];
        if (pos) t += pos[(size_t)row * DM + c];
        if (tok) t += tok[c];
        v[u] = t; s += t;
    }
#pragma unroll
    for (int o = 16; o; o >>= 1) s += __shfl_xor_sync(~0u, s, o);
    float mean = s * (1.f / 768.f), qv = 0.f;
#pragma unroll
    for (int u = 0; u < 24; u++) { float d = v[u] - mean; qv += d * d; }
#pragma unroll
    for (int o = 16; o; o >>= 1) qv += __shfl_xor_sync(~0u, qv, o);
    float inv = rsqrtf(qv * (1.f / 768.f) + 1e-12f);
#pragma unroll
    for (int u = 0; u < 24; u++) {
        int c = lane + u * 32;
        out[(size_t)row * DM + c] = (v[u] - mean) * inv * g[c] + be[c];
    }
}

// ================ flash-mma attention (R12 proven, unchanged) ================
#define PIT2 36
#define PL2 (64 * PIT2)
#define QHIO 0
#define QLOO PL2
#define KHIO (2 * PL2)
#define KLOO (3 * PL2)
#define VHIO (4 * PL2)
#define VLOO (5 * PL2)
#define MSKO (6 * PL2)
#define SMATT ((6 * PL2 + 64) * 4)

__device__ __forceinline__ void stage_rowplane(const float* src, uint32_t* hi,
                                               uint32_t* lo, int tid) {
#pragma unroll
    for (int w = 0; w < 16; w++) {
        int idx = w * 128 + tid;
        int row = idx >> 5, j = idx & 31;
        float2 v = *(const float2*)(src + (size_t)row * DM + 2 * j);
        uint32_t h, l; f16split2(v.x, v.y, h, l);
        hi[row * PIT2 + j] = h; lo[row * PIT2 + j] = l;
    }
}
__device__ __forceinline__ void stage_vt(const float* src, uint32_t* hi,
                                         uint32_t* lo, int tid) {
#pragma unroll
    for (int w = 0; w < 16; w++) {
        int idx = w * 128 + tid;
        int d = idx & 63, j = idx >> 6;
        float v0 = src[(size_t)(2 * j) * DM + d];
        float v1 = src[(size_t)(2 * j + 1) * DM + d];
        uint32_t h, l; f16split2(v0, v1, h, l);
        hi[d * PIT2 + j] = h; lo[d * PIT2 + j] = l;
    }
}

__device__ __forceinline__ void flash_block(
    uint32_t smb, const uint32_t* msk, int lane,
    const uint32_t (&qh)[4][4], const uint32_t (&ql)[4][4],
    float (&oacc)[8][4], float& M0, float& M1, float& L0, float& L1) {
    int q = lane & 3;
    int b_rb = (lane & 7) + ((lane & 16) ? 8 : 0);
    int b_sel = (lane & 8) ? 4 : 0;
    float s[8][4];
#pragma unroll
    for (int t = 0; t < 8; t++)
#pragma unroll
        for (int e = 0; e < 4; e++) s[t][e] = 0.f;
#pragma unroll
    for (int c = 0; c < 4; c++) {
#pragma unroll
        for (int np = 0; np < 4; np++) {
            uint32_t off = (uint32_t)(((np * 16 + b_rb) * PIT2) + c * 8 + b_sel) * 4;
            uint32_t h0, h1, h2, h3, l0, l1, l2, l3;
            ldsm4(h0, h1, h2, h3, smb + KHIO * 4 + off);
            ldsm4(l0, l1, l2, l3, smb + KLOO * 4 + off);
            uint32_t bh0[2] = {h0, h1}, bh1[2] = {h2, h3};
            uint32_t bl0[2] = {l0, l1}, bl1[2] = {l2, l3};
            mmah(s[2*np],   qh[c], bh0); mmah(s[2*np],   ql[c], bh0); mmah(s[2*np],   qh[c], bl0);
            mmah(s[2*np+1], qh[c], bh1); mmah(s[2*np+1], ql[c], bh1); mmah(s[2*np+1], qh[c], bl1);
        }
    }
#pragma unroll
    for (int t = 0; t < 8; t++) {
        int c0 = t * 8 + 2 * q;
        bool m0 = msk[c0] != 0, m1 = msk[c0 + 1] != 0;
        s[t][0] = m0 ? s[t][0] * SCL : NEGV;
        s[t][1] = m1 ? s[t][1] * SCL : NEGV;
        s[t][2] = m0 ? s[t][2] * SCL : NEGV;
        s[t][3] = m1 ? s[t][3] * SCL : NEGV;
    }
    float mx0 = -3.4e38f, mx1 = -3.4e38f;
#pragma unroll
    for (int t = 0; t < 8; t++) {
        mx0 = fmaxf(mx0, fmaxf(s[t][0], s[t][1]));
        mx1 = fmaxf(mx1, fmaxf(s[t][2], s[t][3]));
    }
    mx0 = fmaxf(mx0, __shfl_xor_sync(~0u, mx0, 1));
    mx0 = fmaxf(mx0, __shfl_xor_sync(~0u, mx0, 2));
    mx1 = fmaxf(mx1, __shfl_xor_sync(~0u, mx1, 1));
    mx1 = fmaxf(mx1, __shfl_xor_sync(~0u, mx1, 2));
    float nM0 = fmaxf(M0, mx0), nM1 = fmaxf(M1, mx1);
    float cr0 = __expf(M0 - nM0), cr1 = __expf(M1 - nM1);
    float r0 = 0.f, r1 = 0.f;
#pragma unroll
    for (int t = 0; t < 8; t++) {
        s[t][0] = __expf(s[t][0] - nM0); s[t][1] = __expf(s[t][1] - nM0);
        s[t][2] = __expf(s[t][2] - nM1); s[t][3] = __expf(s[t][3] - nM1);
        r0 += s[t][0] + s[t][1]; r1 += s[t][2] + s[t][3];
    }
    r0 += __shfl_xor_sync(~0u, r0, 1); r0 += __shfl_xor_sync(~0u, r0, 2);
    r1 += __shfl_xor_sync(~0u, r1, 1); r1 += __shfl_xor_sync(~0u, r1, 2);
    L0 = L0 * cr0 + r0; L1 = L1 * cr1 + r1; M0 = nM0; M1 = nM1;
#pragma unroll
    for (int t = 0; t < 8; t++) {
        oacc[t][0] *= cr0; oacc[t][1] *= cr0;
        oacc[t][2] *= cr1; oacc[t][3] *= cr1;
    }
#pragma unroll
    for (int kc = 0; kc < 4; kc++) {
        int t0 = 2 * kc, t1 = t0 + 1;
        uint32_t pa[4], pl[4];
        pa[0] = f16pack2(s[t0][0], s[t0][1]);
        pa[1] = f16pack2(s[t0][2], s[t0][3]);
        pa[2] = f16pack2(s[t1][0], s[t1][1]);
        pa[3] = f16pack2(s[t1][2], s[t1][3]);
        {
            float2 f;
            f = h2f2(pa[0]); pl[0] = f16pack2(s[t0][0] - f.x, s[t0][1] - f.y);
            f = h2f2(pa[1]); pl[1] = f16pack2(s[t0][2] - f.x, s[t0][3] - f.y);
            f = h2f2(pa[2]); pl[2] = f16pack2(s[t1][0] - f.x, s[t1][1] - f.y);
            f = h2f2(pa[3]); pl[3] = f16pack2(s[t1][2] - f.x, s[t1][3] - f.y);
        }
#pragma unroll
        for (int np = 0; np < 4; np++) {
            uint32_t off = (uint32_t)(((np * 16 + b_rb) * PIT2) + kc * 8 + b_sel) * 4;
            uint32_t h0, h1, h2, h3, l0, l1, l2, l3;
            ldsm4(h0, h1, h2, h3, smb + VHIO * 4 + off);
            ldsm4(l0, l1, l2, l3, smb + VLOO * 4 + off);
            uint32_t bh0[2] = {h0, h1}, bh1[2] = {h2, h3};
            uint32_t bl0[2] = {l0, l1}, bl1[2] = {l2, l3};
            mmah(oacc[2*np],   pa, bh0); mmah(oacc[2*np],   pl, bh0); mmah(oacc[2*np],   pa, bl0);
            mmah(oacc[2*np+1], pa, bh1); mmah(oacc[2*np+1], pl, bh1); mmah(oacc[2*np+1], pa, bl1);
        }
    }
}

__global__ __launch_bounds__(128)
void gflashm(const float* __restrict__ Q, const float* __restrict__ K,
             const float* __restrict__ V, const int* __restrict__ am,
             float* __restrict__ part, float* __restrict__ ml) {
    int hg = blockIdx.x, pt = blockIdx.y, h = hg >> 1;
    int qb = (hg & 1) ? (SQ - 64) : 0;
    extern __shared__ uint32_t sm[];
    int tid = threadIdx.x, lane = tid & 31, wid = tid >> 5;
    uint32_t smb = (uint32_t)__cvta_generic_to_shared(sm);
    stage_rowplane(Q + (size_t)qb * DM + h * DH, sm + QHIO, sm + QLOO, tid);
    __syncthreads();
    uint32_t qh[4][4], ql[4][4];
    {
        int a_row = wid * 16 + (lane & 15);
        int a_sel = (lane & 16) ? 4 : 0;
#pragma unroll
        for (int c = 0; c < 4; c++) {
            uint32_t off = (uint32_t)(a_row * PIT2 + c * 8 + a_sel) * 4;
            ldsm4(qh[c][0], qh[c][1], qh[c][2], qh[c][3], smb + QHIO * 4 + off);
            ldsm4(ql[c][0], ql[c][1], ql[c][2], ql[c][3], smb + QLOO * 4 + off);
        }
    }
    float oacc[8][4];
#pragma unroll
    for (int t = 0; t < 8; t++)
#pragma unroll
        for (int e = 0; e < 4; e++) oacc[t][e] = 0.f;
    float M0 = -3.4e38f, M1 = -3.4e38f, L0 = 0.f, L1 = 0.f;
    int nkb = 64 / NSPL;
    for (int kb = pt * nkb; kb < pt * nkb + nkb; kb++) {
        stage_rowplane(K + (size_t)(kb * 64) * DM + h * DH, sm + KHIO, sm + KLOO, tid);
        stage_vt(V + (size_t)(kb * 64) * DM + h * DH, sm + VHIO, sm + VLOO, tid);
        if (tid < 64) sm[MSKO + tid] = (am[kb * 64 + tid] > 0) ? 1u : 0u;
        __syncthreads();
        flash_block(smb, sm + MSKO, lane, qh, ql, oacc, M0, M1, L0, L1);
        __syncthreads();
    }
    float* dst = part + ((size_t)(pt * 24 + hg) << 12);
    int g = lane >> 2, q = lane & 3;
    int r0 = wid * 16 + g, r1 = r0 + 8;
#pragma unroll
    for (int t = 0; t < 8; t++) {
        int col = t * 8 + 2 * q;
        float2 w0 = {oacc[t][0], oacc[t][1]};
        float2 w1 = {oacc[t][2], oacc[t][3]};
        *(float2*)&dst[r0 * 64 + col] = w0;
        *(float2*)&dst[r1 * 64 + col] = w1;
    }
    if (q == 0) {
        int base = (pt * 24 + hg) * 128;
        ml[base + r0] = M0; ml[base + 64 + r0] = L0;
        ml[base + r1] = M1; ml[base + 64 + r1] = L1;
    }
}

__global__ __launch_bounds__(256)
void gflash_red(const float* __restrict__ part, const float* __restrict__ ml,
                float* __restrict__ O) {
    int idx = blockIdx.x * 256 + threadIdx.x;
    int hg = idx >> 12, off = idx & 4095;
    int h = hg >> 1, qb = (hg & 1) ? (SQ - 64) : 0;
    int r = off >> 6, c = off & 63;
    float Mv[NSPL], Lv[NSPL];
    float gM = -3.4e38f;
#pragma unroll
    for (int pt = 0; pt < NSPL; pt++) {
        Mv[pt] = ml[(pt * 24 + hg) * 128 + r];
        Lv[pt] = ml[(pt * 24 + hg) * 128 + 64 + r];
        gM = fmaxf(gM, Mv[pt]);
    }
    float Lt = 0.f, s = 0.f;
#pragma unroll
    for (int pt = 0; pt < NSPL; pt++) {
        float w = __expf(Mv[pt] - gM);
        Lt += Lv[pt] * w;
        s += part[((size_t)(pt * 24 + hg) << 12) + off] * w;
    }
    O[(size_t)(qb + r) * DM + h * DH + c] = s / Lt;
}

__global__ __launch_bounds__(128)
void midattnm(const float* __restrict__ Q, const float* __restrict__ K,
              const float* __restrict__ V, const int* __restrict__ am,
              float* __restrict__ O, PlanParam plan) {
    int im = blockIdx.x, h = blockIdx.y;
    int i = im + 1;
    extern __shared__ uint32_t sm[];
    int tid = threadIdx.x, lane = tid & 31, wid = tid >> 5;
    uint32_t smb = (uint32_t)__cvta_generic_to_shared(sm);
    int blk[8];
    blk[0] = 0; blk[1] = i - 1; blk[2] = i; blk[3] = i + 1; blk[4] = 63;
    blk[5] = plan.rnd[h][im][0]; blk[6] = plan.rnd[h][im][1]; blk[7] = plan.rnd[h][im][2];
    bool vld[8] = {true, i != 1, true, true, i != 62, true, true, true};
    stage_rowplane(Q + (size_t)(i * 64) * DM + h * DH, sm + QHIO, sm + QLOO, tid);
    __syncthreads();
    uint32_t qh[4][4], ql[4][4];
    {
        int a_row = wid * 16 + (lane & 15);
        int a_sel = (lane & 16) ? 4 : 0;
#pragma unroll
        for (int c = 0; c < 4; c++) {
            uint32_t off = (uint32_t)(a_row * PIT2 + c * 8 + a_sel) * 4;
            ldsm4(qh[c][0], qh[c][1], qh[c][2], qh[c][3], smb + QHIO * 4 + off);
            ldsm4(ql[c][0], ql[c][1], ql[c][2], ql[c][3], smb + QLOO * 4 + off);
        }
    }
    float oacc[8][4];
#pragma unroll
    for (int t = 0; t < 8; t++)
#pragma unroll
        for (int e = 0; e < 4; e++) oacc[t][e] = 0.f;
    float M0 = -3.4e38f, M1 = -3.4e38f, L0 = 0.f, L1 = 0.f;
    for (int c = 0; c < 8; c++) {
        stage_rowplane(K + (size_t)(blk[c] * 64) * DM + h * DH, sm + KHIO, sm + KLOO, tid);
        stage_vt(V + (size_t)(blk[c] * 64) * DM + h * DH, sm + VHIO, sm + VLOO, tid);
        if (tid < 64) sm[MSKO + tid] = (vld[c] && am[blk[c] * 64 + tid] > 0) ? 1u : 0u;
        __syncthreads();
        flash_block(smb, sm + MSKO, lane, qh, ql, oacc, M0, M1, L0, L1);
        __syncthreads();
    }
    float inv0 = 1.f / L0, inv1 = 1.f / L1;
    int g = lane >> 2, q = lane & 3;
    int r0 = wid * 16 + g, r1 = r0 + 8;
#pragma unroll
    for (int t = 0; t < 8; t++) {
        int col = t * 8 + 2 * q;
        float2 w0 = {oacc[t][0] * inv0, oacc[t][1] * inv0};
        float2 w1 = {oacc[t][2] * inv1, oacc[t][3] * inv1};
        *(float2*)&O[(size_t)(i * 64 + r0) * DM + h * DH + col] = w0;
        *(float2*)&O[(size_t)(i * 64 + r1) * DM + h * DH + col] = w1;
    }
}

// ------------------------------ classifier ----------------------------------
__global__ __launch_bounds__(512)
void cls_fc1(const float* __restrict__ h, const float* __restrict__ W,
             const float* __restrict__ b, float* __restrict__ o) {
    int n = threadIdx.x;
    float s = b[n];
    for (int k = 0; k < DM; k++) s += h[k] * W[(size_t)k * 512 + n];
    o[n] = fmaxf(s, 0.f);
}
__global__ __launch_bounds__(256)
void cls_fc2(const float* __restrict__ h1, const float* __restrict__ W,
             const float* __restrict__ b, float* __restrict__ o) {
    int n = blockIdx.x * 256 + threadIdx.x;
    if (n >= 2000) return;
    float s = b[n];
    for (int k = 0; k < 512; k++) s += h1[k] * W[(size_t)k * 2000 + n];
    o[n] = s;
}

// ------------------------------ launch --------------------------------------
extern "C" void kernel_launch(void* const* d_in, const int* in_sizes, int n_in,
                              void* d_out, int out_size) {
    const float* x    = (const float*)d_in[0];
    const int*   am   = (const int*)d_in[1];
    const float* Wp   = (const float*)d_in[2];
    const float* bp   = (const float*)d_in[3];
    const float* pos  = (const float*)d_in[4];
    const float* tok  = (const float*)d_in[5];
    const float* lng  = (const float*)d_in[6];
    const float* lnb  = (const float*)d_in[7];
    const float* Wq   = (const float*)d_in[8];
    const float* bq   = (const float*)d_in[9];
    const float* Wk   = (const float*)d_in[10];
    const float* bk   = (const float*)d_in[11];
    const float* Wv   = (const float*)d_in[12];
    const float* bv   = (const float*)d_in[13];
    const float* Wo   = (const float*)d_in[14];
    const float* bo   = (const float*)d_in[15];
    const float* l1g  = (const float*)d_in[16];
    const float* l1b  = (const float*)d_in[17];
    const float* W1   = (const float*)d_in[18];
    const float* b1f  = (const float*)d_in[19];
    const float* W2   = (const float*)d_in[20];
    const float* b2f  = (const float*)d_in[21];
    const float* l2g  = (const float*)d_in[22];
    const float* l2b  = (const float*)d_in[23];
    const float* Wc1  = (const float*)d_in[24];
    const float* bc1  = (const float*)d_in[25];
    const float* Wc2  = (const float*)d_in[26];
    const float* bc2  = (const float*)d_in[27];

    float *h, *q, *k, *v, *attn, *proj, *ffn, *gpvp, *gml, *h1;
    cudaGetSymbolAddress((void**)&h, g_h);
    cudaGetSymbolAddress((void**)&q, g_q);
    cudaGetSymbolAddress((void**)&k, g_k);
    cudaGetSymbolAddress((void**)&v, g_v);
    cudaGetSymbolAddress((void**)&attn, g_attn);
    cudaGetSymbolAddress((void**)&proj, g_proj);
    cudaGetSymbolAddress((void**)&ffn, g_ffn);
    cudaGetSymbolAddress((void**)&gpvp, g_gpvp);
    cudaGetSymbolAddress((void**)&gml, g_gml);
    cudaGetSymbolAddress((void**)&h1, g_h1);

    cudaFuncSetAttribute(gflashm, cudaFuncAttributeMaxDynamicSharedMemorySize, SMATT);
    cudaFuncSetAttribute(midattnm, cudaFuncAttributeMaxDynamicSharedMemorySize, SMATT);
    int smgemm = 2 * BUFU * 4;
    cudaFuncSetAttribute(tgemm, cudaFuncAttributeMaxDynamicSharedMemorySize, smgemm);
    cudaFuncSetAttribute(tgemm3, cudaFuncAttributeMaxDynamicSharedMemorySize, smgemm);

    dim3 gP(DM / 64, SQ / 128);
    dim3 gF(FFD / 64, SQ / 128);
    dim3 gQKV(DM / 64, SQ / 128, 3);

    tgemm<<<gP, 256, smgemm>>>(x, Wp, bp, proj, SQ, DM, 1280, 0);
    add_ln<<<SQ / 8, 256>>>(h, proj, nullptr, pos, tok, lng, lnb);

    for (int l = 0; l < 12; l++) {
        const float* wq = Wq + (size_t)l*DM*DM; const float* bql = bq + (size_t)l*DM;
        const float* wk = Wk + (size_t)l*DM*DM; const float* bkl = bk + (size_t)l*DM;
        const float* wv = Wv + (size_t)l*DM*DM; const float* bvl = bv + (size_t)l*DM;
        const float* wo = Wo + (size_t)l*DM*DM; const float* bol = bo + (size_t)l*DM;
        const float* w1 = W1 + (size_t)l*DM*FFD; const float* b1l = b1f + (size_t)l*FFD;
        const float* w2 = W2 + (size_t)l*FFD*DM; const float* b2l = b2f + (size_t)l*DM;

        tgemm3<<<gQKV, 256, smgemm>>>(h, wq, wk, wv, bql, bkl, bvl, q, k, v, DM, DM);

        gflashm<<<dim3(24, NSPL), 128, SMATT>>>(q, k, v, am, gpvp, gml);
        gflash_red<<<(24 * 4096) / 256, 256>>>(gpvp, gml, attn);
        midattnm<<<dim3(62, 12), 128, SMATT>>>(q, k, v, am, attn, g_plan);

        tgemm<<<gP, 256, smgemm>>>(attn, wo, bol, proj, SQ, DM, DM, 0);
        add_ln<<<SQ / 8, 256>>>(h, h, proj, nullptr, nullptr, l1g + (size_t)l*DM, l1b + (size_t)l*DM);
        tgemm<<<gF, 256, smgemm>>>(h, w1, b1l, ffn, SQ, FFD, DM, 1);
        tgemm<<<gP, 256, smgemm>>>(ffn, w2, b2l, proj, SQ, DM, FFD, 0);
        add_ln<<<SQ / 8, 256>>>(h, h, proj, nullptr, nullptr, l2g + (size_t)l*DM, l2b + (size_t)l*DM);
    }

    cls_fc1<<<1, 512>>>(h, Wc1, bc1, h1);
    cls_fc2<<<8, 256>>>(h1, Wc2, bc2, (float*)d_out);
}

// round 16
// speedup vs baseline: 1.0870x; 1.0312x over previous
#include <cuda_runtime.h>
#include <cuda_fp16.h>
#include <cstdint>
#include <math.h>

#define SQ 4096
#define DM 768
#define FFD 3072
#define NH 12
#define DH 64
#define NMID 62
#define SCL 0.125f
#define NEGV (-1000000000.0f)
#define NSPL 16

__device__ float g_h[SQ * DM];
__device__ float g_q[SQ * DM];
__device__ float g_k[SQ * DM];
__device__ float g_v[SQ * DM];
__device__ float g_attn[SQ * DM];
__device__ float g_proj[SQ * DM];
__device__ float g_ffn[SQ * FFD];
__device__ float g_gpvp[NSPL * 24 * 64 * 64];
__device__ float g_gml[NSPL * 24 * 128];
__device__ float g_h1[512];

struct PlanParam { unsigned char rnd[NH][NMID][3]; };

namespace {
struct MT {
    uint32_t mt[624]; int mti;
    void seed(uint32_t s) {
        mt[0] = s;
        for (int i = 1; i < 624; i++)
            mt[i] = 1812433253u * (mt[i-1] ^ (mt[i-1] >> 30)) + (uint32_t)i;
        mti = 624;
    }
    uint32_t next() {
        if (mti >= 624) {
            for (int i = 0; i < 624; i++) {
                uint32_t y = (mt[i] & 0x80000000u) | (mt[(i+1)%624] & 0x7fffffffu);
                mt[i] = mt[(i+397)%624] ^ (y >> 1) ^ ((y & 1u) ? 0x9908b0dfu : 0u);
            }
            mti = 0;
        }
        uint32_t y = mt[mti++];
        y ^= y >> 11; y ^= (y << 7) & 0x9d2c5680u;
        y ^= (y << 15) & 0xefc60000u; y ^= y >> 18;
        return y;
    }
    uint32_t interval(uint32_t mx) {
        if (!mx) return 0;
        uint32_t m = mx;
        m |= m>>1; m |= m>>2; m |= m>>4; m |= m>>8; m |= m>>16;
        uint32_t v;
        while ((v = (next() & m)) > mx) {}
        return v;
    }
};
PlanParam build_plan() {
    PlanParam P; MT r; r.seed(0u);
    for (int h = 0; h < NH; h++)
        for (int i = 1; i <= NMID; i++) {
            bool inb[64] = {};
            inb[0] = inb[i-1] = inb[i] = inb[i+1] = inb[63] = true;
            int cand[64], nc = 0;
            for (int j = 1; j < 63; j++) if (!inb[j]) cand[nc++] = j;
            int perm[64];
            for (int t = 0; t < nc; t++) perm[t] = t;
            for (int t = nc - 1; t > 0; t--) {
                int j2 = (int)r.interval((uint32_t)t);
                int tmp = perm[t]; perm[t] = perm[j2]; perm[j2] = tmp;
            }
            for (int q = 0; q < 3; q++)
                P.rnd[h][i-1][q] = (unsigned char)cand[perm[q]];
        }
    return P;
}
PlanParam g_plan = build_plan();
}

__device__ __forceinline__ float gelu_t(float x) {
    float x3 = x * x * x;
    return 0.5f * x * (1.0f + tanhf(0.7978845608028654f * (x + 0.044715f * x3)));
}
__device__ __forceinline__ uint32_t f16pack2(float x0, float x1) {
    __half2 h = __floats2half2_rn(x0, x1);
    return *reinterpret_cast<uint32_t*>(&h);
}
__device__ __forceinline__ void f16split2(float x0, float x1, uint32_t& hi, uint32_t& lo) {
    __half2 h = __floats2half2_rn(x0, x1);
    hi = *reinterpret_cast<uint32_t*>(&h);
    float2 hf = __half22float2(h);
    __half2 l = __floats2half2_rn(x0 - hf.x, x1 - hf.y);
    lo = *reinterpret_cast<uint32_t*>(&l);
}
__device__ __forceinline__ float2 h2f2(uint32_t u) {
    __half2 h = *reinterpret_cast<__half2*>(&u);
    return __half22float2(h);
}
__device__ __forceinline__ void mmah(float* c, const uint32_t* a, const uint32_t* b) {
    asm("mma.sync.aligned.m16n8k16.row.col.f32.f16.f16.f32 "
        "{%0,%1,%2,%3},{%4,%5,%6,%7},{%8,%9},{%0,%1,%2,%3};"
        : "+f"(c[0]), "+f"(c[1]), "+f"(c[2]), "+f"(c[3])
        : "r"(a[0]), "r"(a[1]), "r"(a[2]), "r"(a[3]), "r"(b[0]), "r"(b[1]));
}
__device__ __forceinline__ void ldsm4(uint32_t& r0, uint32_t& r1, uint32_t& r2,
                                      uint32_t& r3, uint32_t addr) {
    asm volatile("ldmatrix.sync.aligned.m8n8.x4.shared.b16 {%0,%1,%2,%3}, [%4];"
                 : "=r"(r0), "=r"(r1), "=r"(r2), "=r"(r3) : "r"(addr));
}

// ---------------- fp16x2 tensor GEMM (R10 proven, unchanged) ----------------
#define PIT 20
#define APL (128 * PIT)
#define BPL (64 * PIT)
#define BUFU (APL + 2 * BPL)

__device__ __forceinline__ void tgemm_body(
    const float* __restrict__ A, const float* __restrict__ B,
    const float* __restrict__ bias, float* __restrict__ C,
    int N, int K, int act, int rb, int cb, uint32_t* smu) {
    int tid = threadIdx.x;
    int lane = tid & 31, wid = tid >> 5;
    int g = lane >> 2, q = lane & 3;
    int wr = (wid & 3) * 32, wc = (wid >> 2) * 32;
    float acc[2][4][4];
#pragma unroll
    for (int mi = 0; mi < 2; mi++)
#pragma unroll
        for (int ni = 0; ni < 4; ni++)
#pragma unroll
            for (int e = 0; e < 4; e++) acc[mi][ni][e] = 0.f;
    int arow = tid >> 3, akq = tid & 7;
    int bn = tid & 63, bkg = tid >> 6;
    const float* Bp = B + cb + bn;
    float4 pa[4];
    float pb[8];
    int ntile = K / 32;
    uint32_t sbase = (uint32_t)__cvta_generic_to_shared(smu);
    const uint32_t APLB = APL * 4, BPLB = BPL * 4;
    int a_r = wr + (lane & 15);
    int a_sel = (lane & 16) ? 4 : 0;
    int b_r = wc + (lane & 7) + ((lane & 16) ? 8 : 0);
    int b_sel = (lane & 8) ? 4 : 0;

#define LDAB(k0) { \
    _Pragma("unroll") \
    for (int u = 0; u < 4; u++) \
        pa[u] = *(const float4*)&A[(size_t)(rb + arow + u*32) * K + (k0) + akq*4]; \
    _Pragma("unroll") \
    for (int j = 0; j < 8; j++) \
        pb[j] = Bp[(size_t)((k0) + bkg*8 + j) * N]; }
#define STAB(buf) { \
    uint32_t* Ah = smu + (buf)*BUFU; \
    uint32_t* Bhi = Ah + APL; uint32_t* Blo = Bhi + BPL; \
    _Pragma("unroll") \
    for (int u = 0; u < 4; u++) { \
        uint32_t w0 = f16pack2(pa[u].x, pa[u].y); \
        uint32_t w1 = f16pack2(pa[u].z, pa[u].w); \
        int idx = (arow + u*32) * PIT + akq*2; \
        Ah[idx] = w0; Ah[idx+1] = w1; } \
    _Pragma("unroll") \
    for (int jj = 0; jj < 4; jj++) { \
        uint32_t hh,ll; \
        f16split2(pb[2*jj], pb[2*jj+1], hh, ll); \
        int idx = bn * PIT + bkg*4 + jj; \
        Bhi[idx] = hh; Blo[idx] = ll; } }

    LDAB(0); STAB(0);
    __syncthreads();
    for (int t = 0; t < ntile; t++) {
        int cur = t & 1;
        bool more = (t + 1) < ntile;
        if (more) LDAB((t + 1) * 32);
        uint32_t base = sbase + (uint32_t)cur * BUFU * 4;
#pragma unroll
        for (int s = 0; s < 2; s++) {
            uint32_t av[2][4], bh[4][2], bl[4][2];
#pragma unroll
            for (int mi = 0; mi < 2; mi++) {
                uint32_t off = (uint32_t)(((a_r + mi*16) * PIT) + s*8 + a_sel) * 4;
                ldsm4(av[mi][0], av[mi][1], av[mi][2], av[mi][3], base + off);
            }
#pragma unroll
            for (int np = 0; np < 2; np++) {
                uint32_t off = (uint32_t)(((b_r + np*16) * PIT) + s*8 + b_sel) * 4;
                ldsm4(bh[2*np][0], bh[2*np][1], bh[2*np+1][0], bh[2*np+1][1],
                      base + APLB + off);
                ldsm4(bl[2*np][0], bl[2*np][1], bl[2*np+1][0], bl[2*np+1][1],
                      base + APLB + BPLB + off);
            }
#pragma unroll
            for (int mi = 0; mi < 2; mi++)
#pragma unroll
                for (int ni = 0; ni < 4; ni++) {
                    mmah(acc[mi][ni], av[mi], bh[ni]);
                    mmah(acc[mi][ni], av[mi], bl[ni]);
                }
        }
        if (more) STAB(cur ^ 1);
        __syncthreads();
    }
#pragma unroll
    for (int mi = 0; mi < 2; mi++)
#pragma unroll
        for (int ni = 0; ni < 4; ni++) {
            int col = cb + wc + ni * 8 + 2 * q;
            float b0 = bias[col], b1 = bias[col + 1];
            int r0 = rb + wr + mi * 16 + g;
            float v0 = acc[mi][ni][0] + b0, v1 = acc[mi][ni][1] + b1;
            float v2 = acc[mi][ni][2] + b0, v3 = acc[mi][ni][3] + b1;
            if (act) { v0 = gelu_t(v0); v1 = gelu_t(v1); v2 = gelu_t(v2); v3 = gelu_t(v3); }
            float2 w0 = {v0, v1}, w1 = {v2, v3};
            *(float2*)&C[(size_t)r0 * N + col] = w0;
            *(float2*)&C[(size_t)(r0 + 8) * N + col] = w1;
        }
#undef LDAB
#undef STAB
}

__global__ __launch_bounds__(256, 2)
void tgemm(const float* __restrict__ A, const float* __restrict__ B,
           const float* __restrict__ bias, float* __restrict__ C,
           int M, int N, int K, int act) {
    extern __shared__ uint32_t smu[];
    tgemm_body(A, B, bias, C, N, K, act, blockIdx.y * 128, blockIdx.x * 64, smu);
}
__global__ __launch_bounds__(256, 2)
void tgemm3(const float* __restrict__ A,
            const float* __restrict__ B0, const float* __restrict__ B1,
            const float* __restrict__ B2,
            const float* __restrict__ s0, const float* __restrict__ s1,
            const float* __restrict__ s2,
            float* __restrict__ C0, float* __restrict__ C1,
            float* __restrict__ C2, int N, int K) {
    extern __shared__ uint32_t smu[];
    const float* B = (blockIdx.z == 0) ? B0 : (blockIdx.z == 1) ? B1 : B2;
    const float* s = (blockIdx.z == 0) ? s0 : (blockIdx.z == 1) ? s1 : s2;
    float* C = (blockIdx.z == 0) ? C0 : (blockIdx.z == 1) ? C1 : C2;
    tgemm_body(A, B, s, C, N, K, 0, blockIdx.y * 128, blockIdx.x * 64, smu);
}

// ------------------- add + LayerNorm: one warp per row ----------------------
__global__ __launch_bounds__(256)
void add_ln(float* __restrict__ out, const float* __restrict__ a,
            const float* __restrict__ b, const float* __restrict__ pos,
            const float* __restrict__ tok, const float* __restrict__ g,
            const float* __restrict__ be) {
    int row = blockIdx.x * 8 + (threadIdx.x >> 5);
    int lane = threadIdx.x & 31;
    float v[24], s = 0.f;
#pragma unroll
    for (int u = 0; u < 24; u++) {
        int c = lane + u * 32;
        float t = a[(size_t)row * DM + c];
        if (b) t += b[(size_t)row * DM + c];
        if (pos) t += pos[(size_t)row * DM + c];
        if (tok) t += tok[c];
        v[u] = t; s += t;
    }
#pragma unroll
    for (int o = 16; o; o >>= 1) s += __shfl_xor_sync(~0u, s, o);
    float mean = s * (1.f / 768.f), qv = 0.f;
#pragma unroll
    for (int u = 0; u < 24; u++) { float d = v[u] - mean; qv += d * d; }
#pragma unroll
    for (int o = 16; o; o >>= 1) qv += __shfl_xor_sync(~0u, qv, o);
    float inv = rsqrtf(qv * (1.f / 768.f) + 1e-12f);
#pragma unroll
    for (int u = 0; u < 24; u++) {
        int c = lane + u * 32;
        out[(size_t)row * DM + c] = (v[u] - mean) * inv * g[c] + be[c];
    }
}

// ================ flash-mma attention (R12 core, occ 3) ======================
#define PIT2 36
#define PL2 (64 * PIT2)
#define QHIO 0
#define QLOO PL2
#define KHIO (2 * PL2)
#define KLOO (3 * PL2)
#define VHIO (4 * PL2)
#define VLOO (5 * PL2)
#define MSKO (6 * PL2)
#define SMATT ((6 * PL2 + 64) * 4)

__device__ __forceinline__ void stage_rowplane(const float* src, uint32_t* hi,
                                               uint32_t* lo, int tid) {
#pragma unroll
    for (int w = 0; w < 16; w++) {
        int idx = w * 128 + tid;
        int row = idx >> 5, j = idx & 31;
        float2 v = *(const float2*)(src + (size_t)row * DM + 2 * j);
        uint32_t h, l; f16split2(v.x, v.y, h, l);
        hi[row * PIT2 + j] = h; lo[row * PIT2 + j] = l;
    }
}
__device__ __forceinline__ void stage_vt(const float* src, uint32_t* hi,
                                         uint32_t* lo, int tid) {
#pragma unroll
    for (int w = 0; w < 16; w++) {
        int idx = w * 128 + tid;
        int d = idx & 63, j = idx >> 6;
        float v0 = src[(size_t)(2 * j) * DM + d];
        float v1 = src[(size_t)(2 * j + 1) * DM + d];
        uint32_t h, l; f16split2(v0, v1, h, l);
        hi[d * PIT2 + j] = h; lo[d * PIT2 + j] = l;
    }
}

__device__ __forceinline__ void flash_block(
    uint32_t smb, const uint32_t* msk, int lane,
    const uint32_t (&qh)[4][4], const uint32_t (&ql)[4][4],
    float (&oacc)[8][4], float& M0, float& M1, float& L0, float& L1) {
    int q = lane & 3;
    int b_rb = (lane & 7) + ((lane & 16) ? 8 : 0);
    int b_sel = (lane & 8) ? 4 : 0;
    float s[8][4];
#pragma unroll
    for (int t = 0; t < 8; t++)
#pragma unroll
        for (int e = 0; e < 4; e++) s[t][e] = 0.f;
#pragma unroll
    for (int c = 0; c < 4; c++) {
#pragma unroll
        for (int np = 0; np < 4; np++) {
            uint32_t off = (uint32_t)(((np * 16 + b_rb) * PIT2) + c * 8 + b_sel) * 4;
            uint32_t h0, h1, h2, h3, l0, l1, l2, l3;
            ldsm4(h0, h1, h2, h3, smb + KHIO * 4 + off);
            ldsm4(l0, l1, l2, l3, smb + KLOO * 4 + off);
            uint32_t bh0[2] = {h0, h1}, bh1[2] = {h2, h3};
            uint32_t bl0[2] = {l0, l1}, bl1[2] = {l2, l3};
            mmah(s[2*np],   qh[c], bh0); mmah(s[2*np],   ql[c], bh0); mmah(s[2*np],   qh[c], bl0);
            mmah(s[2*np+1], qh[c], bh1); mmah(s[2*np+1], ql[c], bh1); mmah(s[2*np+1], qh[c], bl1);
        }
    }
#pragma unroll
    for (int t = 0; t < 8; t++) {
        int c0 = t * 8 + 2 * q;
        bool m0 = msk[c0] != 0, m1 = msk[c0 + 1] != 0;
        s[t][0] = m0 ? s[t][0] * SCL : NEGV;
        s[t][1] = m1 ? s[t][1] * SCL : NEGV;
        s[t][2] = m0 ? s[t][2] * SCL : NEGV;
        s[t][3] = m1 ? s[t][3] * SCL : NEGV;
    }
    float mx0 = -3.4e38f, mx1 = -3.4e38f;
#pragma unroll
    for (int t = 0; t < 8; t++) {
        mx0 = fmaxf(mx0, fmaxf(s[t][0], s[t][1]));
        mx1 = fmaxf(mx1, fmaxf(s[t][2], s[t][3]));
    }
    mx0 = fmaxf(mx0, __shfl_xor_sync(~0u, mx0, 1));
    mx0 = fmaxf(mx0, __shfl_xor_sync(~0u, mx0, 2));
    mx1 = fmaxf(mx1, __shfl_xor_sync(~0u, mx1, 1));
    mx1 = fmaxf(mx1, __shfl_xor_sync(~0u, mx1, 2));
    float nM0 = fmaxf(M0, mx0), nM1 = fmaxf(M1, mx1);
    float cr0 = __expf(M0 - nM0), cr1 = __expf(M1 - nM1);
    float r0 = 0.f, r1 = 0.f;
#pragma unroll
    for (int t = 0; t < 8; t++) {
        s[t][0] = __expf(s[t][0] - nM0); s[t][1] = __expf(s[t][1] - nM0);
        s[t][2] = __expf(s[t][2] - nM1); s[t][3] = __expf(s[t][3] - nM1);
        r0 += s[t][0] + s[t][1]; r1 += s[t][2] + s[t][3];
    }
    r0 += __shfl_xor_sync(~0u, r0, 1); r0 += __shfl_xor_sync(~0u, r0, 2);
    r1 += __shfl_xor_sync(~0u, r1, 1); r1 += __shfl_xor_sync(~0u, r1, 2);
    L0 = L0 * cr0 + r0; L1 = L1 * cr1 + r1; M0 = nM0; M1 = nM1;
#pragma unroll
    for (int t = 0; t < 8; t++) {
        oacc[t][0] *= cr0; oacc[t][1] *= cr0;
        oacc[t][2] *= cr1; oacc[t][3] *= cr1;
    }
#pragma unroll
    for (int kc = 0; kc < 4; kc++) {
        int t0 = 2 * kc, t1 = t0 + 1;
        uint32_t pa[4], pl[4];
        pa[0] = f16pack2(s[t0][0], s[t0][1]);
        pa[1] = f16pack2(s[t0][2], s[t0][3]);
        pa[2] = f16pack2(s[t1][0], s[t1][1]);
        pa[3] = f16pack2(s[t1][2], s[t1][3]);
        {
            float2 f;
            f = h2f2(pa[0]); pl[0] = f16pack2(s[t0][0] - f.x, s[t0][1] - f.y);
            f = h2f2(pa[1]); pl[1] = f16pack2(s[t0][2] - f.x, s[t0][3] - f.y);
            f = h2f2(pa[2]); pl[2] = f16pack2(s[t1][0] - f.x, s[t1][1] - f.y);
            f = h2f2(pa[3]); pl[3] = f16pack2(s[t1][2] - f.x, s[t1][3] - f.y);
        }
#pragma unroll
        for (int np = 0; np < 4; np++) {
            uint32_t off = (uint32_t)(((np * 16 + b_rb) * PIT2) + kc * 8 + b_sel) * 4;
            uint32_t h0, h1, h2, h3, l0, l1, l2, l3;
            ldsm4(h0, h1, h2, h3, smb + VHIO * 4 + off);
            ldsm4(l0, l1, l2, l3, smb + VLOO * 4 + off);
            uint32_t bh0[2] = {h0, h1}, bh1[2] = {h2, h3};
            uint32_t bl0[2] = {l0, l1}, bl1[2] = {l2, l3};
            mmah(oacc[2*np],   pa, bh0); mmah(oacc[2*np],   pl, bh0); mmah(oacc[2*np],   pa, bl0);
            mmah(oacc[2*np+1], pa, bh1); mmah(oacc[2*np+1], pl, bh1); mmah(oacc[2*np+1], pa, bl1);
        }
    }
}

__global__ __launch_bounds__(128, 3)
void gflashm(const float* __restrict__ Q, const float* __restrict__ K,
             const float* __restrict__ V, const int* __restrict__ am,
             float* __restrict__ part, float* __restrict__ ml) {
    int hg = blockIdx.x, pt = blockIdx.y, h = hg >> 1;
    int qb = (hg & 1) ? (SQ - 64) : 0;
    extern __shared__ uint32_t sm[];
    int tid = threadIdx.x, lane = tid & 31, wid = tid >> 5;
    uint32_t smb = (uint32_t)__cvta_generic_to_shared(sm);
    stage_rowplane(Q + (size_t)qb * DM + h * DH, sm + QHIO, sm + QLOO, tid);
    __syncthreads();
    uint32_t qh[4][4], ql[4][4];
    {
        int a_row = wid * 16 + (lane & 15);
        int a_sel = (lane & 16) ? 4 : 0;
#pragma unroll
        for (int c = 0; c < 4; c++) {
            uint32_t off = (uint32_t)(a_row * PIT2 + c * 8 + a_sel) * 4;
            ldsm4(qh[c][0], qh[c][1], qh[c][2], qh[c][3], smb + QHIO * 4 + off);
            ldsm4(ql[c][0], ql[c][1], ql[c][2], ql[c][3], smb + QLOO * 4 + off);
        }
    }
    float oacc[8][4];
#pragma unroll
    for (int t = 0; t < 8; t++)
#pragma unroll
        for (int e = 0; e < 4; e++) oacc[t][e] = 0.f;
    float M0 = -3.4e38f, M1 = -3.4e38f, L0 = 0.f, L1 = 0.f;
    int nkb = 64 / NSPL;
    for (int kb = pt * nkb; kb < pt * nkb + nkb; kb++) {
        stage_rowplane(K + (size_t)(kb * 64) * DM + h * DH, sm + KHIO, sm + KLOO, tid);
        stage_vt(V + (size_t)(kb * 64) * DM + h * DH, sm + VHIO, sm + VLOO, tid);
        if (tid < 64) sm[MSKO + tid] = (am[kb * 64 + tid] > 0) ? 1u : 0u;
        __syncthreads();
        flash_block(smb, sm + MSKO, lane, qh, ql, oacc, M0, M1, L0, L1);
        __syncthreads();
    }
    float* dst = part + ((size_t)(pt * 24 + hg) << 12);
    int g = lane >> 2, q = lane & 3;
    int r0 = wid * 16 + g, r1 = r0 + 8;
#pragma unroll
    for (int t = 0; t < 8; t++) {
        int col = t * 8 + 2 * q;
        float2 w0 = {oacc[t][0], oacc[t][1]};
        float2 w1 = {oacc[t][2], oacc[t][3]};
        *(float2*)&dst[r0 * 64 + col] = w0;
        *(float2*)&dst[r1 * 64 + col] = w1;
    }
    if (q == 0) {
        int base = (pt * 24 + hg) * 128;
        ml[base + r0] = M0; ml[base + 64 + r0] = L0;
        ml[base + r1] = M1; ml[base + 64 + r1] = L1;
    }
}

__global__ __launch_bounds__(256)
void gflash_red(const float* __restrict__ part, const float* __restrict__ ml,
                float* __restrict__ O) {
    int idx = blockIdx.x * 256 + threadIdx.x;
    int hg = idx >> 12, off = idx & 4095;
    int h = hg >> 1, qb = (hg & 1) ? (SQ - 64) : 0;
    int r = off >> 6, c = off & 63;
    float Mv[NSPL], Lv[NSPL];
    float gM = -3.4e38f;
#pragma unroll
    for (int pt = 0; pt < NSPL; pt++) {
        Mv[pt] = ml[(pt * 24 + hg) * 128 + r];
        Lv[pt] = ml[(pt * 24 + hg) * 128 + 64 + r];
        gM = fmaxf(gM, Mv[pt]);
    }
    float Lt = 0.f, s = 0.f;
#pragma unroll
    for (int pt = 0; pt < NSPL; pt++) {
        float w = __expf(Mv[pt] - gM);
        Lt += Lv[pt] * w;
        s += part[((size_t)(pt * 24 + hg) << 12) + off] * w;
    }
    O[(size_t)(qb + r) * DM + h * DH + c] = s / Lt;
}

__global__ __launch_bounds__(128, 3)
void midattnm(const float* __restrict__ Q, const float* __restrict__ K,
              const float* __restrict__ V, const int* __restrict__ am,
              float* __restrict__ O, PlanParam plan) {
    int im = blockIdx.x, h = blockIdx.y;
    int i = im + 1;
    extern __shared__ uint32_t sm[];
    int tid = threadIdx.x, lane = tid & 31, wid = tid >> 5;
    uint32_t smb = (uint32_t)__cvta_generic_to_shared(sm);
    int blk[8];
    blk[0] = 0; blk[1] = i - 1; blk[2] = i; blk[3] = i + 1; blk[4] = 63;
    blk[5] = plan.rnd[h][im][0]; blk[6] = plan.rnd[h][im][1]; blk[7] = plan.rnd[h][im][2];
    bool vld[8] = {true, i != 1, true, true, i != 62, true, true, true};
    stage_rowplane(Q + (size_t)(i * 64) * DM + h * DH, sm + QHIO, sm + QLOO, tid);
    __syncthreads();
    uint32_t qh[4][4], ql[4][4];
    {
        int a_row = wid * 16 + (lane & 15);
        int a_sel = (lane & 16) ? 4 : 0;
#pragma unroll
        for (int c = 0; c < 4; c++) {
            uint32_t off = (uint32_t)(a_row * PIT2 + c * 8 + a_sel) * 4;
            ldsm4(qh[c][0], qh[c][1], qh[c][2], qh[c][3], smb + QHIO * 4 + off);
            ldsm4(ql[c][0], ql[c][1], ql[c][2], ql[c][3], smb + QLOO * 4 + off);
        }
    }
    float oacc[8][4];
#pragma unroll
    for (int t = 0; t < 8; t++)
#pragma unroll
        for (int e = 0; e < 4; e++) oacc[t][e] = 0.f;
    float M0 = -3.4e38f, M1 = -3.4e38f, L0 = 0.f, L1 = 0.f;
    for (int c = 0; c < 8; c++) {
        stage_rowplane(K + (size_t)(blk[c] * 64) * DM + h * DH, sm + KHIO, sm + KLOO, tid);
        stage_vt(V + (size_t)(blk[c] * 64) * DM + h * DH, sm + VHIO, sm + VLOO, tid);
        if (tid < 64) sm[MSKO + tid] = (vld[c] && am[blk[c] * 64 + tid] > 0) ? 1u : 0u;
        __syncthreads();
        flash_block(smb, sm + MSKO, lane, qh, ql, oacc, M0, M1, L0, L1);
        __syncthreads();
    }
    float inv0 = 1.f / L0, inv1 = 1.f / L1;
    int g = lane >> 2, q = lane & 3;
    int r0 = wid * 16 + g, r1 = r0 + 8;
#pragma unroll
    for (int t = 0; t < 8; t++) {
        int col = t * 8 + 2 * q;
        float2 w0 = {oacc[t][0] * inv0, oacc[t][1] * inv0};
        float2 w1 = {oacc[t][2] * inv1, oacc[t][3] * inv1};
        *(float2*)&O[(size_t)(i * 64 + r0) * DM + h * DH + col] = w0;
        *(float2*)&O[(size_t)(i * 64 + r1) * DM + h * DH + col] = w1;
    }
}

// ------------------------------ classifier ----------------------------------
__global__ __launch_bounds__(512)
void cls_fc1(const float* __restrict__ h, const float* __restrict__ W,
             const float* __restrict__ b, float* __restrict__ o) {
    int n = threadIdx.x;
    float s = b[n];
    for (int k = 0; k < DM; k++) s += h[k] * W[(size_t)k * 512 + n];
    o[n] = fmaxf(s, 0.f);
}
__global__ __launch_bounds__(256)
void cls_fc2(const float* __restrict__ h1, const float* __restrict__ W,
             const float* __restrict__ b, float* __restrict__ o) {
    int n = blockIdx.x * 256 + threadIdx.x;
    if (n >= 2000) return;
    float s = b[n];
    for (int k = 0; k < 512; k++) s += h1[k] * W[(size_t)k * 2000 + n];
    o[n] = s;
}

// ------------------------------ launch --------------------------------------
extern "C" void kernel_launch(void* const* d_in, const int* in_sizes, int n_in,
                              void* d_out, int out_size) {
    const float* x    = (const float*)d_in[0];
    const int*   am   = (const int*)d_in[1];
    const float* Wp   = (const float*)d_in[2];
    const float* bp   = (const float*)d_in[3];
    const float* pos  = (const float*)d_in[4];
    const float* tok  = (const float*)d_in[5];
    const float* lng  = (const float*)d_in[6];
    const float* lnb  = (const float*)d_in[7];
    const float* Wq   = (const float*)d_in[8];
    const float* bq   = (const float*)d_in[9];
    const float* Wk   = (const float*)d_in[10];
    const float* bk   = (const float*)d_in[11];
    const float* Wv   = (const float*)d_in[12];
    const float* bv   = (const float*)d_in[13];
    const float* Wo   = (const float*)d_in[14];
    const float* bo   = (const float*)d_in[15];
    const float* l1g  = (const float*)d_in[16];
    const float* l1b  = (const float*)d_in[17];
    const float* W1   = (const float*)d_in[18];
    const float* b1f  = (const float*)d_in[19];
    const float* W2   = (const float*)d_in[20];
    const float* b2f  = (const float*)d_in[21];
    const float* l2g  = (const float*)d_in[22];
    const float* l2b  = (const float*)d_in[23];
    const float* Wc1  = (const float*)d_in[24];
    const float* bc1  = (const float*)d_in[25];
    const float* Wc2  = (const float*)d_in[26];
    const float* bc2  = (const float*)d_in[27];

    float *h, *q, *k, *v, *attn, *proj, *ffn, *gpvp, *gml, *h1;
    cudaGetSymbolAddress((void**)&h, g_h);
    cudaGetSymbolAddress((void**)&q, g_q);
    cudaGetSymbolAddress((void**)&k, g_k);
    cudaGetSymbolAddress((void**)&v, g_v);
    cudaGetSymbolAddress((void**)&attn, g_attn);
    cudaGetSymbolAddress((void**)&proj, g_proj);
    cudaGetSymbolAddress((void**)&ffn, g_ffn);
    cudaGetSymbolAddress((void**)&gpvp, g_gpvp);
    cudaGetSymbolAddress((void**)&gml, g_gml);
    cudaGetSymbolAddress((void**)&h1, g_h1);

    cudaFuncSetAttribute(gflashm, cudaFuncAttributeMaxDynamicSharedMemorySize, SMATT);
    cudaFuncSetAttribute(midattnm, cudaFuncAttributeMaxDynamicSharedMemorySize, SMATT);
    int smgemm = 2 * BUFU * 4;
    cudaFuncSetAttribute(tgemm, cudaFuncAttributeMaxDynamicSharedMemorySize, smgemm);
    cudaFuncSetAttribute(tgemm3, cudaFuncAttributeMaxDynamicSharedMemorySize, smgemm);

    dim3 gP(DM / 64, SQ / 128);
    dim3 gF(FFD / 64, SQ / 128);
    dim3 gQKV(DM / 64, SQ / 128, 3);

    tgemm<<<gP, 256, smgemm>>>(x, Wp, bp, proj, SQ, DM, 1280, 0);
    add_ln<<<SQ / 8, 256>>>(h, proj, nullptr, pos, tok, lng, lnb);

    for (int l = 0; l < 12; l++) {
        const float* wq = Wq + (size_t)l*DM*DM; const float* bql = bq + (size_t)l*DM;
        const float* wk = Wk + (size_t)l*DM*DM; const float* bkl = bk + (size_t)l*DM;
        const float* wv = Wv + (size_t)l*DM*DM; const float* bvl = bv + (size_t)l*DM;
        const float* wo = Wo + (size_t)l*DM*DM; const float* bol = bo + (size_t)l*DM;
        const float* w1 = W1 + (size_t)l*DM*FFD; const float* b1l = b1f + (size_t)l*FFD;
        const float* w2 = W2 + (size_t)l*FFD*DM; const float* b2l = b2f + (size_t)l*DM;

        tgemm3<<<gQKV, 256, smgemm>>>(h, wq, wk, wv, bql, bkl, bvl, q, k, v, DM, DM);

        gflashm<<<dim3(24, NSPL), 128, SMATT>>>(q, k, v, am, gpvp, gml);
        gflash_red<<<(24 * 4096) / 256, 256>>>(gpvp, gml, attn);
        midattnm<<<dim3(62, 12), 128, SMATT>>>(q, k, v, am, attn, g_plan);

        tgemm<<<gP, 256, smgemm>>>(attn, wo, bol, proj, SQ, DM, DM, 0);
        add_ln<<<SQ / 8, 256>>>(h, h, proj, nullptr, nullptr, l1g + (size_t)l*DM, l1b + (size_t)l*DM);
        tgemm<<<gF, 256, smgemm>>>(h, w1, b1l, ffn, SQ, FFD, DM, 1);
        tgemm<<<gP, 256, smgemm>>>(ffn, w2, b2l, proj, SQ, DM, FFD, 0);
        add_ln<<<SQ / 8, 256>>>(h, h, proj, nullptr, nullptr, l2g + (size_t)l*DM, l2b + (size_t)l*DM);
    }

    cls_fc1<<<1, 512>>>(h, Wc1, bc1, h1);
    cls_fc2<<<8, 256>>>(h1, Wc2, bc2, (float*)d_out);
}